// round 14
// baseline (speedup 1.0000x reference)
#include <cuda_runtime.h>
#include <cstdint>

// Problem constants
#define BATCH   512
#define DIMC    64
#define BOOK    1024
#define EMB     64
#define CWDIM   (DIMC * EMB)            // 4096

// Output layout (floats): cw | one_hot | new_codebook | new_ema
#define CW_OFF    0
#define CW_SIZE   (BATCH * CWDIM)                    // 2,097,152
#define OH_OFF    (CW_OFF + CW_SIZE)
#define OH_SIZE   (BATCH * DIMC * BOOK)              // 33,554,432
#define NCB_OFF   (OH_OFF + OH_SIZE)
#define NCB_SIZE  (DIMC * BOOK * EMB)                // 4,194,304
#define NEMA_OFF  (NCB_OFF + NCB_SIZE)
#define NEMA_SIZE (DIMC * BOOK)

// per-(b,d,kq) partial argmin keys: (sortable_dist<<32)|k — plain stores,
// no init needed (every slot written every launch), merged by the last CTA.
__device__ unsigned long long g_part[BATCH * DIMC * 4];
// per-d completion counter; persistent across replays, checked mod 16.
__device__ int g_cnt[DIMC];

static __device__ __forceinline__ unsigned long long pack2(float v) {
    unsigned long long r;
    asm("mov.b64 %0, {%1, %1};" : "=l"(r) : "r"(__float_as_uint(v)));
    return r;
}

// ---------------------------------------------------------------------------
// Single fused kernel. Grid (16, 64): blockIdx.x = {mt: row tile, kq: k
// quarter}, blockIdx.y = d. 256 threads, SMEM as R13.
//
// Prep is d-CLOSED: this CTA zeroes one_hot[b in mt-tile][d][k in kq-quarter]
// and DECAY-inits ncb/nema rows k in [kq*256+mt*64, +64) of d. Hence the 16
// CTAs of a d collectively complete ALL state that d's scatter needs.
// After g_part stores: threadfence + atomicAdd(g_cnt[d]); the last of 16
// performs the scatter for all 512 (b,d) pairs of this d.
// ---------------------------------------------------------------------------
extern __shared__ float sm_dyn[];

__global__ void __launch_bounds__(256, 2)
argmin_kernel(const float* __restrict__ x, const float* __restrict__ cb,
              const float* __restrict__ ema, float* __restrict__ out)
{
    const float DECAYF = 0.999f;
    float* xs  = sm_dyn;              // 64*130
    float* cs  = sm_dyn + 64 * 130;   // 64*65
    float* bsq = cs + 64 * 65;        // 64

    const int t  = threadIdx.x;
    const int mt = blockIdx.x & 3;          // row tile
    const int kq = blockIdx.x >> 2;         // k quarter: tiles kq*4..kq*4+3
    const int d  = blockIdx.y;
    const int b0 = mt * 128;

    // ---- fused output prep, d-closed (fire-and-forget stores) ----
    {
        // one_hot zero: b in [b0,b0+128), k in [kq*256, kq*256+256)
        float4 z = make_float4(0.f, 0.f, 0.f, 0.f);
        float4* oh4 = (float4*)(out + OH_OFF);
        #pragma unroll 4
        for (int it = 0; it < 32; ++it) {
            int idx   = t + it * 256;         // 0..8191
            int b_off = idx >> 6;             // 0..127
            int col   = idx & 63;             // f4 col within quarter
            oh4[((size_t)(b0 + b_off) * DIMC + d) * 256 + kq * 64 + col] = z;
        }

        // ncb init: rows k in [kbase, kbase+64) of d, all e
        const int kbase = kq * 256 + mt * 64;
        const float4* cb4  = (const float4*)cb;
        float4*       ncb4 = (float4*)(out + NCB_OFF);
        size_t nb = ((size_t)d * BOOK + kbase) * 16;   // f4 units
        #pragma unroll 4
        for (int it = 0; it < 4; ++it) {
            float4 v = cb4[nb + t + it * 256];
            v.x *= DECAYF; v.y *= DECAYF; v.z *= DECAYF; v.w *= DECAYF;
            ncb4[nb + t + it * 256] = v;
        }
        // nema init: same 64-k range
        if (t < 16) {
            const float4* em4 = (const float4*)ema;
            float4*       ne4 = (float4*)(out + NEMA_OFF);
            size_t eb = (size_t)d * 256 + kbase / 4 + t;
            float4 v = em4[eb];
            v.x *= DECAYF; v.y *= DECAYF; v.z *= DECAYF; v.w *= DECAYF;
            ne4[eb] = v;
        }
    }

    // ---- load x tile, transposed into xs[e][row] ----
    #pragma unroll
    for (int it = 0; it < 8; ++it) {
        int idx = t + it * 256;       // 0..2047
        int row = idx >> 4;           // 0..127
        int e4  = (idx & 15) * 4;
        float4 v = *(const float4*)(x + (size_t)(b0 + row) * CWDIM + d * EMB + e4);
        xs[(e4 + 0) * 130 + row] = v.x;
        xs[(e4 + 1) * 130 + row] = v.y;
        xs[(e4 + 2) * 130 + row] = v.z;
        xs[(e4 + 3) * 130 + row] = v.w;
    }

    const int tr = t >> 4, tc = t & 15;
    float bestS[8];
    int   bestI[8];
    #pragma unroll
    for (int m = 0; m < 8; ++m) { bestS[m] = 3.4e38f; bestI[m] = 0; }

    const float* cbd = cb + (size_t)d * (BOOK * EMB);

    for (int kt = kq * 4; kt < kq * 4 + 4; ++kt) {
        __syncthreads();   // protect cs/bsq from previous tile's readers
        // load 64 x 64 codebook k-tile into cs[k][e] (pad 65)
        #pragma unroll
        for (int it = 0; it < 4; ++it) {
            int idx = t + it * 256;   // 0..1023
            int kk  = idx >> 4;       // 0..63
            int e4  = (idx & 15) * 4;
            float4 v = *(const float4*)(cbd + (size_t)(kt * 64 + kk) * EMB + e4);
            cs[kk * 65 + e4 + 0] = v.x;
            cs[kk * 65 + e4 + 1] = v.y;
            cs[kk * 65 + e4 + 2] = v.z;
            cs[kk * 65 + e4 + 3] = v.w;
        }
        __syncthreads();
        if (t < 64) {
            float s = 0.f;
            #pragma unroll
            for (int e = 0; e < EMB; ++e) { float c = cs[t * 65 + e]; s = fmaf(c, c, s); }
            bsq[t] = s;
        }
        __syncthreads();

        unsigned long long acc[4][4];
        #pragma unroll
        for (int i = 0; i < 4; ++i)
            #pragma unroll
            for (int j = 0; j < 4; ++j) acc[i][j] = 0ull;

        #pragma unroll 4
        for (int e = 0; e < EMB; ++e) {
            unsigned long long a2[4];
            #pragma unroll
            for (int i = 0; i < 4; ++i)
                a2[i] = *(const unsigned long long*)(xs + e * 130 + 2 * (tr + 16 * i));
            #pragma unroll
            for (int j = 0; j < 4; ++j) {
                unsigned long long bb = pack2(cs[(tc + 16 * j) * 65 + e]);
                #pragma unroll
                for (int i = 0; i < 4; ++i)
                    asm("fma.rn.f32x2 %0, %1, %2, %0;"
                        : "+l"(acc[i][j]) : "l"(a2[i]), "l"(bb));
            }
        }

        // epilogue: score = bsq[k] - 2*dot  (x_sq omitted: constant per row)
        #pragma unroll
        for (int j = 0; j < 4; ++j) {
            int kk = tc + 16 * j;
            int k  = kt * 64 + kk;
            float bq = bsq[kk];
            #pragma unroll
            for (int i = 0; i < 4; ++i) {
                unsigned int ulo, uhi;
                asm("mov.b64 {%0, %1}, %2;" : "=r"(ulo), "=r"(uhi) : "l"(acc[i][j]));
                float s0 = fmaf(-2.f, __uint_as_float(ulo), bq);
                float s1 = fmaf(-2.f, __uint_as_float(uhi), bq);
                if (s0 < bestS[2 * i])     { bestS[2 * i]     = s0; bestI[2 * i]     = k; }
                if (s1 < bestS[2 * i + 1]) { bestS[2 * i + 1] = s1; bestI[2 * i + 1] = k; }
            }
        }
    }

    // reduce across the 16 tc threads (half-warp), ties -> lowest index,
    // then plain-store this k-quarter's key into g_part.
    #pragma unroll
    for (int m = 0; m < 8; ++m) {
        float s  = bestS[m];
        int   ki = bestI[m];
        #pragma unroll
        for (int off = 8; off > 0; off >>= 1) {
            float os = __shfl_down_sync(0xffffffffu, s,  off, 16);
            int   oi = __shfl_down_sync(0xffffffffu, ki, off, 16);
            if (os < s || (os == s && oi < ki)) { s = os; ki = oi; }
        }
        if (tc == 0) {
            int row = 2 * (tr + 16 * (m >> 1)) + (m & 1);
            unsigned us = __float_as_uint(s);
            us = (s < 0.f) ? ~us : (us | 0x80000000u);
            unsigned long long key = ((unsigned long long)us << 32) | (unsigned)ki;
            g_part[(((size_t)(b0 + row) * DIMC) + d) * 4 + kq] = key;
        }
    }

    // ---- completion counter; last of 16 CTAs of this d does the scatter ----
    __threadfence();                 // release all our stores (device scope)
    __shared__ int s_last;
    if (t == 0) {
        int old = atomicAdd(&g_cnt[d], 1);
        s_last = ((old & 15) == 15);   // replay-safe: exactly 16 adds/launch
    }
    __syncthreads();
    if (!s_last) return;
    __threadfence();                 // acquire side

    // ---- scatter for all 512 (b, d) pairs of this d ----
    {
        const float GAINF = (float)(1.0 - 0.999);
        const float EPSF  = 1e-6f;
        float* cw   = out + CW_OFF;
        float* oh   = out + OH_OFF;
        float* ncb  = out + NCB_OFF;
        float* nema = out + NEMA_OFF;

        const int warp = t >> 5, lane = t & 31;
        const float emabase_g = GAINF;   // alias to keep names clear

        for (int g = 0; g < 16; ++g) {
            int   kk4[4], bb4[4];
            float gg4[4];
            #pragma unroll
            for (int q = 0; q < 4; ++q) {
                int b = warp * 64 + g * 4 + q;     // this warp's b range
                const unsigned long long* pp =
                    &g_part[((size_t)b * DIMC + d) * 4];
                unsigned long long k0 = __ldcg(pp + 0);
                unsigned long long k1 = __ldcg(pp + 1);
                unsigned long long k2 = __ldcg(pp + 2);
                unsigned long long k3 = __ldcg(pp + 3);
                unsigned long long key = min(min(k0, k1), min(k2, k3));
                kk4[q] = (int)(unsigned)(key & 0xFFFFFFFFull);
                bb4[q] = b;
            }
            #pragma unroll
            for (int q = 0; q < 4; ++q)
                gg4[q] = emabase_g / (ema[d * BOOK + kk4[q]] + EPSF);

            #pragma unroll
            for (int q = 0; q < 4; ++q) {
                int b = bb4[q], k = kk4[q];
                size_t co = ((size_t)d * BOOK + k) * EMB + 2 * lane;
                size_t xo = (size_t)b * CWDIM + d * EMB + 2 * lane;
                float2 c2 = *(const float2*)(cb + co);
                float2 x2 = *(const float2*)(x + xo);

                // cw = x + (c - x): mirror reference fp order exactly
                float2 wv;
                wv.x = x2.x + (c2.x - x2.x);
                wv.y = x2.y + (c2.y - x2.y);
                *(float2*)(cw + xo) = wv;

                atomicAdd(ncb + co,     gg4[q] * x2.x);
                atomicAdd(ncb + co + 1, gg4[q] * x2.y);

                if (lane == 0) {
                    oh[(size_t)b * (DIMC * BOOK) + (size_t)d * BOOK + k] = 1.0f;
                    atomicAdd(nema + d * BOOK + k, GAINF);
                }
            }
        }
    }
}

// ---------------------------------------------------------------------------
extern "C" void kernel_launch(void* const* d_in, const int* in_sizes, int n_in,
                              void* d_out, int out_size)
{
    (void)in_sizes; (void)n_in; (void)out_size;
    const float* x   = (const float*)d_in[0];
    const float* cb  = (const float*)d_in[1];
    const float* ema = (const float*)d_in[2];
    float* out = (float*)d_out;

    const int smem = (64 * 130 + 64 * 65 + 64) * (int)sizeof(float);  // 50432 B
    cudaFuncSetAttribute(argmin_kernel,
                         cudaFuncAttributeMaxDynamicSharedMemorySize, smem);

    dim3 grid(16, 64);
    argmin_kernel<<<grid, 256, smem>>>(x, cb, ema, out);
}

// round 15
// speedup vs baseline: 1.3443x; 1.3443x over previous
#include <cuda_runtime.h>
#include <cstdint>

// Problem constants
#define BATCH   512
#define DIMC    64
#define BOOK    1024
#define EMB     64
#define CWDIM   (DIMC * EMB)            // 4096

// Output layout (floats): cw | one_hot | new_codebook | new_ema
#define CW_OFF    0
#define CW_SIZE   (BATCH * CWDIM)                    // 2,097,152
#define OH_OFF    (CW_OFF + CW_SIZE)
#define OH_SIZE   (BATCH * DIMC * BOOK)              // 33,554,432
#define NCB_OFF   (OH_OFF + OH_SIZE)
#define NCB_SIZE  (DIMC * BOOK * EMB)                // 4,194,304
#define NEMA_OFF  (NCB_OFF + NCB_SIZE)
#define NEMA_SIZE (DIMC * BOOK)

// per-(b,d,kq) partial argmin keys: (sortable_dist<<32)|k — plain stores,
// no init needed (every slot written every launch), merged in scatter.
__device__ unsigned long long g_part[BATCH * DIMC * 4];

static __device__ __forceinline__ unsigned long long pack2(float v) {
    unsigned long long r;
    asm("mov.b64 %0, {%1, %1};" : "=l"(r) : "r"(__float_as_uint(v)));
    return r;
}

// ---------------------------------------------------------------------------
// Kernel 1: BYTE-IDENTICAL to R13 (argmin at 98% of the scalar-FMA floor).
// Grid: (16, 64) — blockIdx.x = {mt: row tile, kq: k quarter}, blockIdx.y=d.
// SMEM: xs[e][row] 64x130 f32; cs[k][e] 64x65 f32; bsq[64].
// Thread (tr,tc)=(t>>4,t&15): 4 row-pairs (8 rows) x 4 codes per 64-k tile.
// Fused one_hot zero + ncb/nema DECAY-init (1/1024 share per CTA, upfront).
// ---------------------------------------------------------------------------
extern __shared__ float sm_dyn[];

__global__ void __launch_bounds__(256, 2)
argmin_kernel(const float* __restrict__ x, const float* __restrict__ cb,
              const float* __restrict__ ema, float* __restrict__ out)
{
    const float DECAYF = 0.999f;
    float* xs  = sm_dyn;              // 64*130
    float* cs  = sm_dyn + 64 * 130;   // 64*65
    float* bsq = cs + 64 * 65;        // 64

    const int t  = threadIdx.x;
    const int mt = blockIdx.x & 3;          // row tile
    const int kq = blockIdx.x >> 2;         // k quarter: tiles kq*4..kq*4+3
    const int d  = blockIdx.y;
    const int b0 = mt * 128;
    const int blk = d * 16 + blockIdx.x;    // 0..1023

    // ---- fused output prep (fire-and-forget stores, hidden under compute) ----
    {
        float4 z = make_float4(0.f, 0.f, 0.f, 0.f);
        float4* oh4 = (float4*)(out + OH_OFF);
        size_t base = (size_t)blk * (OH_SIZE / 1024 / 4);   // 8192 f4 per blk
        #pragma unroll 4
        for (int it = 0; it < 32; ++it)
            oh4[base + t + it * 256] = z;

        const float4* cb4  = (const float4*)cb;
        float4*       ncb4 = (float4*)(out + NCB_OFF);
        size_t cbase = (size_t)blk * (NCB_SIZE / 1024 / 4); // 1024 f4 per blk
        #pragma unroll 4
        for (int it = 0; it < 4; ++it) {
            float4 v = cb4[cbase + t + it * 256];
            v.x *= DECAYF; v.y *= DECAYF; v.z *= DECAYF; v.w *= DECAYF;
            ncb4[cbase + t + it * 256] = v;
        }
        if (t < 16) {
            const float4* em4 = (const float4*)ema;
            float4*       ne4 = (float4*)(out + NEMA_OFF);
            size_t eb = (size_t)blk * 16 + t;              // 16384 f4 total
            float4 v = em4[eb];
            v.x *= DECAYF; v.y *= DECAYF; v.z *= DECAYF; v.w *= DECAYF;
            ne4[eb] = v;
        }
    }

    // ---- load x tile, transposed into xs[e][row] ----
    #pragma unroll
    for (int it = 0; it < 8; ++it) {
        int idx = t + it * 256;       // 0..2047
        int row = idx >> 4;           // 0..127
        int e4  = (idx & 15) * 4;
        float4 v = *(const float4*)(x + (size_t)(b0 + row) * CWDIM + d * EMB + e4);
        xs[(e4 + 0) * 130 + row] = v.x;
        xs[(e4 + 1) * 130 + row] = v.y;
        xs[(e4 + 2) * 130 + row] = v.z;
        xs[(e4 + 3) * 130 + row] = v.w;
    }

    const int tr = t >> 4, tc = t & 15;
    float bestS[8];
    int   bestI[8];
    #pragma unroll
    for (int m = 0; m < 8; ++m) { bestS[m] = 3.4e38f; bestI[m] = 0; }

    const float* cbd = cb + (size_t)d * (BOOK * EMB);

    for (int kt = kq * 4; kt < kq * 4 + 4; ++kt) {
        __syncthreads();   // protect cs/bsq from previous tile's readers
        // load 64 x 64 codebook k-tile into cs[k][e] (pad 65)
        #pragma unroll
        for (int it = 0; it < 4; ++it) {
            int idx = t + it * 256;   // 0..1023
            int kk  = idx >> 4;       // 0..63
            int e4  = (idx & 15) * 4;
            float4 v = *(const float4*)(cbd + (size_t)(kt * 64 + kk) * EMB + e4);
            cs[kk * 65 + e4 + 0] = v.x;
            cs[kk * 65 + e4 + 1] = v.y;
            cs[kk * 65 + e4 + 2] = v.z;
            cs[kk * 65 + e4 + 3] = v.w;
        }
        __syncthreads();
        if (t < 64) {
            float s = 0.f;
            #pragma unroll
            for (int e = 0; e < EMB; ++e) { float c = cs[t * 65 + e]; s = fmaf(c, c, s); }
            bsq[t] = s;
        }
        __syncthreads();

        unsigned long long acc[4][4];
        #pragma unroll
        for (int i = 0; i < 4; ++i)
            #pragma unroll
            for (int j = 0; j < 4; ++j) acc[i][j] = 0ull;

        #pragma unroll 4
        for (int e = 0; e < EMB; ++e) {
            unsigned long long a2[4];
            #pragma unroll
            for (int i = 0; i < 4; ++i)
                a2[i] = *(const unsigned long long*)(xs + e * 130 + 2 * (tr + 16 * i));
            #pragma unroll
            for (int j = 0; j < 4; ++j) {
                unsigned long long bb = pack2(cs[(tc + 16 * j) * 65 + e]);
                #pragma unroll
                for (int i = 0; i < 4; ++i)
                    asm("fma.rn.f32x2 %0, %1, %2, %0;"
                        : "+l"(acc[i][j]) : "l"(a2[i]), "l"(bb));
            }
        }

        // epilogue: score = bsq[k] - 2*dot  (x_sq omitted: constant per row)
        #pragma unroll
        for (int j = 0; j < 4; ++j) {
            int kk = tc + 16 * j;
            int k  = kt * 64 + kk;
            float bq = bsq[kk];
            #pragma unroll
            for (int i = 0; i < 4; ++i) {
                unsigned int ulo, uhi;
                asm("mov.b64 {%0, %1}, %2;" : "=r"(ulo), "=r"(uhi) : "l"(acc[i][j]));
                float s0 = fmaf(-2.f, __uint_as_float(ulo), bq);
                float s1 = fmaf(-2.f, __uint_as_float(uhi), bq);
                if (s0 < bestS[2 * i])     { bestS[2 * i]     = s0; bestI[2 * i]     = k; }
                if (s1 < bestS[2 * i + 1]) { bestS[2 * i + 1] = s1; bestI[2 * i + 1] = k; }
            }
        }
    }

    // reduce across the 16 tc threads (half-warp), ties -> lowest index,
    // then plain-store this k-quarter's key into g_part.
    #pragma unroll
    for (int m = 0; m < 8; ++m) {
        float s  = bestS[m];
        int   ki = bestI[m];
        #pragma unroll
        for (int off = 8; off > 0; off >>= 1) {
            float os = __shfl_down_sync(0xffffffffu, s,  off, 16);
            int   oi = __shfl_down_sync(0xffffffffu, ki, off, 16);
            if (os < s || (os == s && oi < ki)) { s = os; ki = oi; }
        }
        if (tc == 0) {
            int row = 2 * (tr + 16 * (m >> 1)) + (m & 1);
            unsigned us = __float_as_uint(s);
            us = (s < 0.f) ? ~us : (us | 0x80000000u);
            unsigned long long key = ((unsigned long long)us << 32) | (unsigned)ki;
            g_part[(((size_t)(b0 + row) * DIMC) + d) * 4 + kq] = key;
        }
    }
}

// ---------------------------------------------------------------------------
// Kernel 2 (v4): ONE (b,d) pair per warp; float4 data path + vector red.
// Lanes 0..3 fetch the 4 partial keys; 2x shfl.xor min-reduce; broadcast k.
// Lanes 0..15 each own one float4 chunk of the 64-float row: load x4/c4,
// store cw4, one red.global.add.v4.f32 into ncb (4x fewer REDG ops).
// ---------------------------------------------------------------------------
__global__ void __launch_bounds__(256)
scatter_kernel(const float* __restrict__ x, const float* __restrict__ cb,
               const float* __restrict__ ema, float* __restrict__ out)
{
    const float GAINF = (float)(1.0 - 0.999);
    const float EPSF  = 1e-6f;
    float* cw   = out + CW_OFF;
    float* oh   = out + OH_OFF;
    float* ncb  = out + NCB_OFF;
    float* nema = out + NEMA_OFF;

    const int w    = blockIdx.x * 8 + (threadIdx.x >> 5);   // 0..32767 = b*64+d
    const int lane = threadIdx.x & 31;
    const int b = w >> 6, d = w & 63;

    // lane-parallel key merge
    unsigned long long key = 0xFFFFFFFFFFFFFFFFull;
    if (lane < 4) key = g_part[(size_t)w * 4 + lane];
    {
        unsigned long long o;
        o = __shfl_xor_sync(0xffffffffu, key, 1); key = min(key, o);
        o = __shfl_xor_sync(0xffffffffu, key, 2); key = min(key, o);
    }
    const int k = (int)(unsigned)(__shfl_sync(0xffffffffu, key, 0) & 0xFFFFFFFFull);

    const float g = GAINF / (ema[d * BOOK + k] + EPSF);

    if (lane < 16) {
        size_t co = ((size_t)d * BOOK + k) * EMB + 4 * lane;
        size_t xo = (size_t)b * CWDIM + d * EMB + 4 * lane;
        float4 c4 = *(const float4*)(cb + co);
        float4 x4 = *(const float4*)(x + xo);

        // cw = x + (c - x): mirror reference fp order exactly
        float4 wv;
        wv.x = x4.x + (c4.x - x4.x);
        wv.y = x4.y + (c4.y - x4.y);
        wv.z = x4.z + (c4.z - x4.z);
        wv.w = x4.w + (c4.w - x4.w);
        *(float4*)(cw + xo) = wv;

        asm volatile("red.global.add.v4.f32 [%0], {%1, %2, %3, %4};"
                     :: "l"(ncb + co),
                        "f"(g * x4.x), "f"(g * x4.y),
                        "f"(g * x4.z), "f"(g * x4.w)
                     : "memory");
    }

    if (lane == 0) {
        oh[(size_t)b * (DIMC * BOOK) + (size_t)d * BOOK + k] = 1.0f;
        atomicAdd(nema + d * BOOK + k, GAINF);
    }
}

// ---------------------------------------------------------------------------
extern "C" void kernel_launch(void* const* d_in, const int* in_sizes, int n_in,
                              void* d_out, int out_size)
{
    (void)in_sizes; (void)n_in; (void)out_size;
    const float* x   = (const float*)d_in[0];
    const float* cb  = (const float*)d_in[1];
    const float* ema = (const float*)d_in[2];
    float* out = (float*)d_out;

    const int smem = (64 * 130 + 64 * 65 + 64) * (int)sizeof(float);  // 50432 B
    cudaFuncSetAttribute(argmin_kernel,
                         cudaFuncAttributeMaxDynamicSharedMemorySize, smem);

    dim3 grid(16, 64);
    argmin_kernel<<<grid, 256, smem>>>(x, cb, ema, out);
    scatter_kernel<<<4096, 256>>>(x, cb, ema, out);
}

// round 16
// speedup vs baseline: 1.3559x; 1.0086x over previous
#include <cuda_runtime.h>
#include <cstdint>

// Problem constants
#define BATCH   512
#define DIMC    64
#define BOOK    1024
#define EMB     64
#define CWDIM   (DIMC * EMB)            // 4096

// Output layout (floats): cw | one_hot | new_codebook | new_ema
#define CW_OFF    0
#define CW_SIZE   (BATCH * CWDIM)                    // 2,097,152
#define OH_OFF    (CW_OFF + CW_SIZE)
#define OH_SIZE   (BATCH * DIMC * BOOK)              // 33,554,432
#define NCB_OFF   (OH_OFF + OH_SIZE)
#define NCB_SIZE  (DIMC * BOOK * EMB)                // 4,194,304
#define NEMA_OFF  (NCB_OFF + NCB_SIZE)
#define NEMA_SIZE (DIMC * BOOK)

// per-(b,d,kq) partial argmin keys: (sortable_dist<<32)|k — plain stores,
// no init needed (every slot written every launch), merged in scatter.
__device__ unsigned long long g_part[BATCH * DIMC * 4];

static __device__ __forceinline__ unsigned long long pack2(float v) {
    unsigned long long r;
    asm("mov.b64 %0, {%1, %1};" : "=l"(r) : "r"(__float_as_uint(v)));
    return r;
}

// ---------------------------------------------------------------------------
// Kernel 1: BYTE-IDENTICAL to R13/R15 (argmin at 98% of the scalar-FMA floor).
// Grid: (16, 64) — blockIdx.x = {mt: row tile, kq: k quarter}, blockIdx.y=d.
// SMEM: xs[e][row] 64x130 f32; cs[k][e] 64x65 f32; bsq[64].
// Thread (tr,tc)=(t>>4,t&15): 4 row-pairs (8 rows) x 4 codes per 64-k tile.
// Fused one_hot zero + ncb/nema DECAY-init (1/1024 share per CTA, upfront).
// ---------------------------------------------------------------------------
extern __shared__ float sm_dyn[];

__global__ void __launch_bounds__(256, 2)
argmin_kernel(const float* __restrict__ x, const float* __restrict__ cb,
              const float* __restrict__ ema, float* __restrict__ out)
{
    const float DECAYF = 0.999f;
    float* xs  = sm_dyn;              // 64*130
    float* cs  = sm_dyn + 64 * 130;   // 64*65
    float* bsq = cs + 64 * 65;        // 64

    const int t  = threadIdx.x;
    const int mt = blockIdx.x & 3;          // row tile
    const int kq = blockIdx.x >> 2;         // k quarter: tiles kq*4..kq*4+3
    const int d  = blockIdx.y;
    const int b0 = mt * 128;
    const int blk = d * 16 + blockIdx.x;    // 0..1023

    // ---- fused output prep (fire-and-forget stores, hidden under compute) ----
    {
        float4 z = make_float4(0.f, 0.f, 0.f, 0.f);
        float4* oh4 = (float4*)(out + OH_OFF);
        size_t base = (size_t)blk * (OH_SIZE / 1024 / 4);   // 8192 f4 per blk
        #pragma unroll 4
        for (int it = 0; it < 32; ++it)
            oh4[base + t + it * 256] = z;

        const float4* cb4  = (const float4*)cb;
        float4*       ncb4 = (float4*)(out + NCB_OFF);
        size_t cbase = (size_t)blk * (NCB_SIZE / 1024 / 4); // 1024 f4 per blk
        #pragma unroll 4
        for (int it = 0; it < 4; ++it) {
            float4 v = cb4[cbase + t + it * 256];
            v.x *= DECAYF; v.y *= DECAYF; v.z *= DECAYF; v.w *= DECAYF;
            ncb4[cbase + t + it * 256] = v;
        }
        if (t < 16) {
            const float4* em4 = (const float4*)ema;
            float4*       ne4 = (float4*)(out + NEMA_OFF);
            size_t eb = (size_t)blk * 16 + t;              // 16384 f4 total
            float4 v = em4[eb];
            v.x *= DECAYF; v.y *= DECAYF; v.z *= DECAYF; v.w *= DECAYF;
            ne4[eb] = v;
        }
    }

    // ---- load x tile, transposed into xs[e][row] ----
    #pragma unroll
    for (int it = 0; it < 8; ++it) {
        int idx = t + it * 256;       // 0..2047
        int row = idx >> 4;           // 0..127
        int e4  = (idx & 15) * 4;
        float4 v = *(const float4*)(x + (size_t)(b0 + row) * CWDIM + d * EMB + e4);
        xs[(e4 + 0) * 130 + row] = v.x;
        xs[(e4 + 1) * 130 + row] = v.y;
        xs[(e4 + 2) * 130 + row] = v.z;
        xs[(e4 + 3) * 130 + row] = v.w;
    }

    const int tr = t >> 4, tc = t & 15;
    float bestS[8];
    int   bestI[8];
    #pragma unroll
    for (int m = 0; m < 8; ++m) { bestS[m] = 3.4e38f; bestI[m] = 0; }

    const float* cbd = cb + (size_t)d * (BOOK * EMB);

    for (int kt = kq * 4; kt < kq * 4 + 4; ++kt) {
        __syncthreads();   // protect cs/bsq from previous tile's readers
        // load 64 x 64 codebook k-tile into cs[k][e] (pad 65)
        #pragma unroll
        for (int it = 0; it < 4; ++it) {
            int idx = t + it * 256;   // 0..1023
            int kk  = idx >> 4;       // 0..63
            int e4  = (idx & 15) * 4;
            float4 v = *(const float4*)(cbd + (size_t)(kt * 64 + kk) * EMB + e4);
            cs[kk * 65 + e4 + 0] = v.x;
            cs[kk * 65 + e4 + 1] = v.y;
            cs[kk * 65 + e4 + 2] = v.z;
            cs[kk * 65 + e4 + 3] = v.w;
        }
        __syncthreads();
        if (t < 64) {
            float s = 0.f;
            #pragma unroll
            for (int e = 0; e < EMB; ++e) { float c = cs[t * 65 + e]; s = fmaf(c, c, s); }
            bsq[t] = s;
        }
        __syncthreads();

        unsigned long long acc[4][4];
        #pragma unroll
        for (int i = 0; i < 4; ++i)
            #pragma unroll
            for (int j = 0; j < 4; ++j) acc[i][j] = 0ull;

        #pragma unroll 4
        for (int e = 0; e < EMB; ++e) {
            unsigned long long a2[4];
            #pragma unroll
            for (int i = 0; i < 4; ++i)
                a2[i] = *(const unsigned long long*)(xs + e * 130 + 2 * (tr + 16 * i));
            #pragma unroll
            for (int j = 0; j < 4; ++j) {
                unsigned long long bb = pack2(cs[(tc + 16 * j) * 65 + e]);
                #pragma unroll
                for (int i = 0; i < 4; ++i)
                    asm("fma.rn.f32x2 %0, %1, %2, %0;"
                        : "+l"(acc[i][j]) : "l"(a2[i]), "l"(bb));
            }
        }

        // epilogue: score = bsq[k] - 2*dot  (x_sq omitted: constant per row)
        #pragma unroll
        for (int j = 0; j < 4; ++j) {
            int kk = tc + 16 * j;
            int k  = kt * 64 + kk;
            float bq = bsq[kk];
            #pragma unroll
            for (int i = 0; i < 4; ++i) {
                unsigned int ulo, uhi;
                asm("mov.b64 {%0, %1}, %2;" : "=r"(ulo), "=r"(uhi) : "l"(acc[i][j]));
                float s0 = fmaf(-2.f, __uint_as_float(ulo), bq);
                float s1 = fmaf(-2.f, __uint_as_float(uhi), bq);
                if (s0 < bestS[2 * i])     { bestS[2 * i]     = s0; bestI[2 * i]     = k; }
                if (s1 < bestS[2 * i + 1]) { bestS[2 * i + 1] = s1; bestI[2 * i + 1] = k; }
            }
        }
    }

    // reduce across the 16 tc threads (half-warp), ties -> lowest index,
    // then plain-store this k-quarter's key into g_part.
    #pragma unroll
    for (int m = 0; m < 8; ++m) {
        float s  = bestS[m];
        int   ki = bestI[m];
        #pragma unroll
        for (int off = 8; off > 0; off >>= 1) {
            float os = __shfl_down_sync(0xffffffffu, s,  off, 16);
            int   oi = __shfl_down_sync(0xffffffffu, ki, off, 16);
            if (os < s || (os == s && oi < ki)) { s = os; ki = oi; }
        }
        if (tc == 0) {
            int row = 2 * (tr + 16 * (m >> 1)) + (m & 1);
            unsigned us = __float_as_uint(s);
            us = (s < 0.f) ? ~us : (us | 0x80000000u);
            unsigned long long key = ((unsigned long long)us << 32) | (unsigned)ki;
            g_part[(((size_t)(b0 + row) * DIMC) + d) * 4 + kq] = key;
        }
    }
}

// ---------------------------------------------------------------------------
// Kernel 2 (v5): TWO (b,d) pairs per warp, one per half-warp — all 32 lanes
// active in the float4 data path (halves LSU instruction count vs v4).
// Sublanes 0..3 of each half merge that pair's 4 partial keys (shfl.xor 1,2
// stays inside the quad); broadcast from lane 0 / 16. Each sublane owns one
// float4 chunk: load x4/c4, store cw4, one red.global.add.v4.f32 into ncb.
// ---------------------------------------------------------------------------
__global__ void __launch_bounds__(256)
scatter_kernel(const float* __restrict__ x, const float* __restrict__ cb,
               const float* __restrict__ ema, float* __restrict__ out)
{
    const float GAINF = (float)(1.0 - 0.999);
    const float EPSF  = 1e-6f;
    float* cw   = out + CW_OFF;
    float* oh   = out + OH_OFF;
    float* ncb  = out + NCB_OFF;
    float* nema = out + NEMA_OFF;

    const int wp   = blockIdx.x * 8 + (threadIdx.x >> 5);   // 0..16383
    const int lane = threadIdx.x & 31;
    const int half = lane >> 4;              // 0 or 1
    const int sub  = lane & 15;
    const int pair = wp * 2 + half;          // 0..32767 = b*64 + d
    const int b = pair >> 6, d = pair & 63;

    // per-half key merge (quad min; lanes 4-15 hold +inf, unused)
    unsigned long long key = 0xFFFFFFFFFFFFFFFFull;
    if (sub < 4) key = g_part[(size_t)pair * 4 + sub];
    {
        unsigned long long o;
        o = __shfl_xor_sync(0xffffffffu, key, 1); key = min(key, o);
        o = __shfl_xor_sync(0xffffffffu, key, 2); key = min(key, o);
    }
    const int k = (int)(unsigned)(__shfl_sync(0xffffffffu, key, half * 16)
                                  & 0xFFFFFFFFull);

    const float g = GAINF / (ema[d * BOOK + k] + EPSF);

    size_t co = ((size_t)d * BOOK + k) * EMB + 4 * sub;
    size_t xo = (size_t)b * CWDIM + d * EMB + 4 * sub;
    float4 c4 = *(const float4*)(cb + co);
    float4 x4 = *(const float4*)(x + xo);

    // cw = x + (c - x): mirror reference fp order exactly
    float4 wv;
    wv.x = x4.x + (c4.x - x4.x);
    wv.y = x4.y + (c4.y - x4.y);
    wv.z = x4.z + (c4.z - x4.z);
    wv.w = x4.w + (c4.w - x4.w);
    *(float4*)(cw + xo) = wv;

    asm volatile("red.global.add.v4.f32 [%0], {%1, %2, %3, %4};"
                 :: "l"(ncb + co),
                    "f"(g * x4.x), "f"(g * x4.y),
                    "f"(g * x4.z), "f"(g * x4.w)
                 : "memory");

    if (sub == 0) {
        oh[(size_t)b * (DIMC * BOOK) + (size_t)d * BOOK + k] = 1.0f;
        atomicAdd(nema + d * BOOK + k, GAINF);
    }
}

// ---------------------------------------------------------------------------
extern "C" void kernel_launch(void* const* d_in, const int* in_sizes, int n_in,
                              void* d_out, int out_size)
{
    (void)in_sizes; (void)n_in; (void)out_size;
    const float* x   = (const float*)d_in[0];
    const float* cb  = (const float*)d_in[1];
    const float* ema = (const float*)d_in[2];
    float* out = (float*)d_out;

    const int smem = (64 * 130 + 64 * 65 + 64) * (int)sizeof(float);  // 50432 B
    cudaFuncSetAttribute(argmin_kernel,
                         cudaFuncAttributeMaxDynamicSharedMemorySize, smem);

    dim3 grid(16, 64);
    argmin_kernel<<<grid, 256, smem>>>(x, cb, ema, out);
    scatter_kernel<<<2048, 256>>>(x, cb, ema, out);
}